// round 2
// baseline (speedup 1.0000x reference)
#include <cuda_runtime.h>
#include <math.h>

#define B_  2
#define M_  2048
#define N_  2048
#define D_  2048
#define NH  16
#define DH  128
#define DR  64

// ---------------- scratch (device globals; no runtime allocation) ------------
__device__ float g_QC[(size_t)B_ * M_ * NH * DH];
__device__ float g_QR[(size_t)B_ * M_ * NH * DR];
__device__ float g_KC[(size_t)B_ * N_ * NH * DH];
__device__ float g_KR[(size_t)B_ * N_ * NH * DR];
__device__ float g_V [(size_t)B_ * N_ * NH * DH];
__device__ float g_AO[(size_t)B_ * M_ * NH * DH];

// ---------------- helpers ----------------------------------------------------
__device__ __forceinline__ unsigned f2tf(float x) {
    unsigned y;
    asm("cvt.rna.tf32.f32 %0, %1;" : "=r"(y) : "f"(x));
    return y;
}

__device__ __forceinline__ void mma8(float* c, const unsigned* a, const unsigned* b) {
    asm volatile(
        "mma.sync.aligned.m16n8k8.row.col.f32.tf32.tf32.f32 "
        "{%0,%1,%2,%3},{%4,%5,%6,%7},{%8,%9},{%0,%1,%2,%3};\n"
        : "+f"(c[0]), "+f"(c[1]), "+f"(c[2]), "+f"(c[3])
        : "r"(a[0]), "r"(a[1]), "r"(a[2]), "r"(a[3]), "r"(b[0]), "r"(b[1]));
}

// ---------------- tf32 GEMM: C[R x Cc] = A[R x K] @ W[Cc x K]^T ---------------
// Block tile 128x128, k-tile 32, 256 threads (8 warps, 4x2), double-buffered smem.
#define GSTR 36   // 32 + 4 pad -> conflict-free fragment loads

__global__ __launch_bounds__(256) void gemm_tf32(
    const float* __restrict__ A, const float* __restrict__ W,
    float* __restrict__ C, int Cc, int K)
{
    extern __shared__ unsigned sm[];
    unsigned* As = sm;                 // [2][128][GSTR]
    unsigned* Bs = sm + 2 * 128 * GSTR;

    const int tid  = threadIdx.x;
    const int lane = tid & 31;
    const int w    = tid >> 5;
    const int gid  = lane >> 2;   // groupID
    const int tig  = lane & 3;    // thread-in-group
    const int wr   = (w >> 1) * 32;
    const int wc   = (w & 1) * 64;
    const size_t brow = (size_t)blockIdx.y * 128;
    const size_t bcol = (size_t)blockIdx.x * 128;

    const float* Ag = A + brow * K;
    const float* Wg = W + bcol * K;

    float acc[2][8][4];
#pragma unroll
    for (int i = 0; i < 2; i++)
#pragma unroll
        for (int j = 0; j < 8; j++)
#pragma unroll
            for (int k = 0; k < 4; k++) acc[i][j][k] = 0.f;

    // preload k-tile 0 into stage 0
#pragma unroll
    for (int i = 0; i < 4; i++) {
        int idx = tid + i * 256;
        int r = idx >> 3, c = (idx & 7) * 4;
        float4 va = *(const float4*)(Ag + (size_t)r * K + c);
        float4 vb = *(const float4*)(Wg + (size_t)r * K + c);
        unsigned* pa = As + r * GSTR + c;
        pa[0] = f2tf(va.x); pa[1] = f2tf(va.y); pa[2] = f2tf(va.z); pa[3] = f2tf(va.w);
        unsigned* pb = Bs + r * GSTR + c;
        pb[0] = f2tf(vb.x); pb[1] = f2tf(vb.y); pb[2] = f2tf(vb.z); pb[3] = f2tf(vb.w);
    }
    __syncthreads();

    const int nk = K >> 5;
    int st = 0;
    for (int kt = 0; kt < nk; ++kt) {
        float4 ra[4], rb[4];
        if (kt + 1 < nk) {
            const float* Ag2 = Ag + (kt + 1) * 32;
            const float* Wg2 = Wg + (kt + 1) * 32;
#pragma unroll
            for (int i = 0; i < 4; i++) {
                int idx = tid + i * 256;
                int r = idx >> 3, c = (idx & 7) * 4;
                ra[i] = *(const float4*)(Ag2 + (size_t)r * K + c);
                rb[i] = *(const float4*)(Wg2 + (size_t)r * K + c);
            }
        }
        const unsigned* Ac = As + st * 128 * GSTR;
        const unsigned* Bc = Bs + st * 128 * GSTR;
#pragma unroll
        for (int kc = 0; kc < 4; ++kc) {
            const int k = kc * 8;
            unsigned af[2][4];
#pragma unroll
            for (int mt = 0; mt < 2; ++mt) {
                const unsigned* p = Ac + (wr + mt * 16 + gid) * GSTR + k + tig;
                af[mt][0] = p[0];
                af[mt][2] = p[4];
                af[mt][1] = p[8 * GSTR];
                af[mt][3] = p[8 * GSTR + 4];
            }
#pragma unroll
            for (int nt = 0; nt < 8; ++nt) {
                unsigned bf[2];
                const unsigned* q = Bc + (wc + nt * 8 + gid) * GSTR + k + tig;
                bf[0] = q[0];
                bf[1] = q[4];
                mma8(acc[0][nt], af[0], bf);
                mma8(acc[1][nt], af[1], bf);
            }
        }
        if (kt + 1 < nk) {
            unsigned* An = As + (st ^ 1) * 128 * GSTR;
            unsigned* Bn = Bs + (st ^ 1) * 128 * GSTR;
#pragma unroll
            for (int i = 0; i < 4; i++) {
                int idx = tid + i * 256;
                int r = idx >> 3, c = (idx & 7) * 4;
                unsigned* pa = An + r * GSTR + c;
                pa[0] = f2tf(ra[i].x); pa[1] = f2tf(ra[i].y); pa[2] = f2tf(ra[i].z); pa[3] = f2tf(ra[i].w);
                unsigned* pb = Bn + r * GSTR + c;
                pb[0] = f2tf(rb[i].x); pb[1] = f2tf(rb[i].y); pb[2] = f2tf(rb[i].z); pb[3] = f2tf(rb[i].w);
            }
        }
        __syncthreads();
        st ^= 1;
    }

#pragma unroll
    for (int mt = 0; mt < 2; ++mt)
#pragma unroll
        for (int nt = 0; nt < 8; ++nt) {
            size_t row = brow + wr + mt * 16 + gid;
            size_t col = bcol + wc + nt * 8 + 2 * tig;
            *(float2*)(C + row * Cc + col)       = make_float2(acc[mt][nt][0], acc[mt][nt][1]);
            *(float2*)(C + (row + 8) * Cc + col) = make_float2(acc[mt][nt][2], acc[mt][nt][3]);
        }
}

// ---------------- RoPE (in-place, interleaved pairs) --------------------------
__global__ void rope_kernel(float* __restrict__ x, int nPairs, int seqmask) {
    int idx = blockIdx.x * blockDim.x + threadIdx.x;
    if (idx >= nPairs) return;
    int tok = idx >> 9;          // NH*DR/2 = 512 pairs per token
    int p   = idx & 511;
    int i   = p & 31;            // pair index within head
    int pos = tok & seqmask;     // position within sequence
    // inv_freq = theta^(-i/32), theta = 1e6 ; ln(1e6) = 13.815511
    float inv = expf(-(float)i * (13.8155106f / 32.0f));
    float ang = (float)pos * inv;
    float s, c;
    sincosf(ang, &s, &c);
    size_t base = (size_t)tok * (NH * DR) + 2 * p;
    float x0 = x[base], x1 = x[base + 1];
    x[base]     = x0 * c - x1 * s;
    x[base + 1] = x1 * c + x0 * s;
}

// ---------------- flash attention (tf32 mma) ----------------------------------
// grid (M/64, NH, B), 128 threads (4 warps). Each warp owns 16 q-rows.
#define QSTR 196   // 192 + 4
#define VSTR 132   // 128 + 4
#define PSTR 68    // 64 + 4
#define LOG2E 1.44269504f

__global__ __launch_bounds__(128) void attn_kernel(
    const float* __restrict__ QC, const float* __restrict__ QR,
    const float* __restrict__ KC, const float* __restrict__ KR,
    const float* __restrict__ Vg, float* __restrict__ AO)
{
    extern __shared__ unsigned sm[];
    unsigned* Qs = sm;                  // [64][QSTR]
    unsigned* Ks = Qs + 64 * QSTR;      // [64][QSTR]
    unsigned* Vs = Ks + 64 * QSTR;      // [64][VSTR]
    unsigned* Ps = Vs + 64 * VSTR;      // [64][PSTR]

    const int tid  = threadIdx.x;
    const int lane = tid & 31;
    const int w    = tid >> 5;
    const int gid  = lane >> 2;
    const int tig  = lane & 3;
    const int m0 = blockIdx.x * 64;
    const int h  = blockIdx.y;
    const int b  = blockIdx.z;
    const float scale = 0.07216878364870323f; // 1/sqrt(192)

    const float* QCb = QC + ((size_t)b * M_ + m0) * (NH * DH) + h * DH;
    const float* QRb = QR + ((size_t)b * M_ + m0) * (NH * DR) + h * DR;
    const float* KCb = KC + (size_t)b * N_ * (NH * DH) + h * DH;
    const float* KRb = KR + (size_t)b * N_ * (NH * DR) + h * DR;
    const float* Vb  = Vg + (size_t)b * N_ * (NH * DH) + h * DH;

    // load Q tile (64 x 192), scale folded in
#pragma unroll
    for (int i = 0; i < 24; i++) {
        int idx = tid + i * 128;
        int r = idx / 48, j = idx % 48;
        float4 v; int col;
        if (j < 32) { v = *(const float4*)(QCb + (size_t)r * (NH * DH) + j * 4); col = j * 4; }
        else        { v = *(const float4*)(QRb + (size_t)r * (NH * DR) + (j - 32) * 4); col = 128 + (j - 32) * 4; }
        unsigned* p = Qs + r * QSTR + col;
        p[0] = f2tf(v.x * scale); p[1] = f2tf(v.y * scale);
        p[2] = f2tf(v.z * scale); p[3] = f2tf(v.w * scale);
    }

    float o[16][4];
#pragma unroll
    for (int i = 0; i < 16; i++)
#pragma unroll
        for (int j = 0; j < 4; j++) o[i][j] = 0.f;
    const float NEG_INF = __int_as_float(0xff800000);
    float mx0 = NEG_INF, mx1 = NEG_INF, l0 = 0.f, l1 = 0.f;

    for (int n0 = 0; n0 < N_; n0 += 64) {
        __syncthreads();   // previous iteration's consumers done
#pragma unroll
        for (int i = 0; i < 24; i++) {
            int idx = tid + i * 128;
            int r = idx / 48, j = idx % 48;
            float4 v; int col;
            if (j < 32) { v = *(const float4*)(KCb + (size_t)(n0 + r) * (NH * DH) + j * 4); col = j * 4; }
            else        { v = *(const float4*)(KRb + (size_t)(n0 + r) * (NH * DR) + (j - 32) * 4); col = 128 + (j - 32) * 4; }
            unsigned* p = Ks + r * QSTR + col;
            p[0] = f2tf(v.x); p[1] = f2tf(v.y); p[2] = f2tf(v.z); p[3] = f2tf(v.w);
        }
#pragma unroll
        for (int i = 0; i < 16; i++) {
            int idx = tid + i * 128;
            int r = idx >> 5, c = (idx & 31) * 4;
            float4 v = *(const float4*)(Vb + (size_t)(n0 + r) * (NH * DH) + c);
            unsigned* p = Vs + r * VSTR + c;
            p[0] = f2tf(v.x); p[1] = f2tf(v.y); p[2] = f2tf(v.z); p[3] = f2tf(v.w);
        }
        __syncthreads();

        // S = Q @ K^T   (warp w: rows 16w..16w+15, cols 0..63)
        float s[8][4];
#pragma unroll
        for (int i = 0; i < 8; i++)
#pragma unroll
            for (int j = 0; j < 4; j++) s[i][j] = 0.f;
#pragma unroll
        for (int kc = 0; kc < 24; ++kc) {
            const int k = kc * 8;
            unsigned af[4];
            const unsigned* p = Qs + (w * 16 + gid) * QSTR + k + tig;
            af[0] = p[0];
            af[2] = p[4];
            af[1] = p[8 * QSTR];
            af[3] = p[8 * QSTR + 4];
#pragma unroll
            for (int nt = 0; nt < 8; ++nt) {
                unsigned bf[2];
                const unsigned* q = Ks + (nt * 8 + gid) * QSTR + k + tig;
                bf[0] = q[0];
                bf[1] = q[4];
                mma8(s[nt], af, bf);
            }
        }

        // online softmax
        float tm0 = NEG_INF, tm1 = NEG_INF;
#pragma unroll
        for (int nt = 0; nt < 8; ++nt) {
            tm0 = fmaxf(tm0, fmaxf(s[nt][0], s[nt][1]));
            tm1 = fmaxf(tm1, fmaxf(s[nt][2], s[nt][3]));
        }
        tm0 = fmaxf(tm0, __shfl_xor_sync(0xffffffffu, tm0, 1));
        tm0 = fmaxf(tm0, __shfl_xor_sync(0xffffffffu, tm0, 2));
        tm1 = fmaxf(tm1, __shfl_xor_sync(0xffffffffu, tm1, 1));
        tm1 = fmaxf(tm1, __shfl_xor_sync(0xffffffffu, tm1, 2));
        float nm0 = fmaxf(mx0, tm0), nm1 = fmaxf(mx1, tm1);
        float a0 = exp2f((mx0 - nm0) * LOG2E);
        float a1 = exp2f((mx1 - nm1) * LOG2E);

        float rs0 = 0.f, rs1 = 0.f;
        unsigned* pr0 = Ps + (w * 16 + gid) * PSTR;
        unsigned* pr1 = pr0 + 8 * PSTR;
#pragma unroll
        for (int nt = 0; nt < 8; ++nt) {
            float p0 = exp2f((s[nt][0] - nm0) * LOG2E);
            float p1 = exp2f((s[nt][1] - nm0) * LOG2E);
            float p2 = exp2f((s[nt][2] - nm1) * LOG2E);
            float p3 = exp2f((s[nt][3] - nm1) * LOG2E);
            rs0 += p0 + p1; rs1 += p2 + p3;
            pr0[nt * 8 + 2 * tig]     = f2tf(p0);
            pr0[nt * 8 + 2 * tig + 1] = f2tf(p1);
            pr1[nt * 8 + 2 * tig]     = f2tf(p2);
            pr1[nt * 8 + 2 * tig + 1] = f2tf(p3);
        }
        rs0 += __shfl_xor_sync(0xffffffffu, rs0, 1);
        rs0 += __shfl_xor_sync(0xffffffffu, rs0, 2);
        rs1 += __shfl_xor_sync(0xffffffffu, rs1, 1);
        rs1 += __shfl_xor_sync(0xffffffffu, rs1, 2);
        l0 = l0 * a0 + rs0;
        l1 = l1 * a1 + rs1;
        mx0 = nm0; mx1 = nm1;
#pragma unroll
        for (int nt = 0; nt < 16; ++nt) {
            o[nt][0] *= a0; o[nt][1] *= a0;
            o[nt][2] *= a1; o[nt][3] *= a1;
        }
        __syncwarp();

        // O += P @ V
#pragma unroll
        for (int kc = 0; kc < 8; ++kc) {
            unsigned af[4];
            const unsigned* p = Ps + (w * 16 + gid) * PSTR + kc * 8 + tig;
            af[0] = p[0];
            af[2] = p[4];
            af[1] = p[8 * PSTR];
            af[3] = p[8 * PSTR + 4];
#pragma unroll
            for (int nt = 0; nt < 16; ++nt) {
                unsigned bf[2];
                const unsigned* q = Vs + (kc * 8 + tig) * VSTR + nt * 8 + gid;
                bf[0] = q[0];
                bf[1] = q[4 * VSTR];
                mma8(o[nt], af, bf);
            }
        }
    }

    // epilogue
    float i0 = 1.f / l0, i1 = 1.f / l1;
    float* O0 = AO + ((size_t)b * M_ + m0 + w * 16 + gid) * (NH * DH) + h * DH;
    float* O1 = O0 + (size_t)8 * (NH * DH);
#pragma unroll
    for (int nt = 0; nt < 16; ++nt) {
        int col = nt * 8 + 2 * tig;
        *(float2*)(O0 + col) = make_float2(o[nt][0] * i0, o[nt][1] * i0);
        *(float2*)(O1 + col) = make_float2(o[nt][2] * i1, o[nt][3] * i1);
    }
}

// ---------------- launcher ----------------------------------------------------
extern "C" void kernel_launch(void* const* d_in, const int* in_sizes, int n_in,
                              void* d_out, int out_size)
{
    const float* query = (const float*)d_in[0];
    const float* kv    = (const float*)d_in[1];
    const float* W_QC  = (const float*)d_in[2];
    const float* W_KC  = (const float*)d_in[3];
    const float* W_QR  = (const float*)d_in[4];
    const float* W_KR  = (const float*)d_in[5];
    const float* W_V   = (const float*)d_in[6];
    const float* W_O   = (const float*)d_in[7];
    float* out = (float*)d_out;

    float *QC, *QR, *KC, *KR, *Vv, *AO;
    cudaGetSymbolAddress((void**)&QC, g_QC);
    cudaGetSymbolAddress((void**)&QR, g_QR);
    cudaGetSymbolAddress((void**)&KC, g_KC);
    cudaGetSymbolAddress((void**)&KR, g_KR);
    cudaGetSymbolAddress((void**)&Vv, g_V);
    cudaGetSymbolAddress((void**)&AO, g_AO);

    const int gemm_smem = 2 * 128 * GSTR * 2 * (int)sizeof(unsigned);          // 73728 B
    const int attn_smem = 64 * (QSTR + QSTR + VSTR + PSTR) * (int)sizeof(unsigned); // 151552 B
    cudaFuncSetAttribute(gemm_tf32, cudaFuncAttributeMaxDynamicSharedMemorySize, gemm_smem);
    cudaFuncSetAttribute(attn_kernel, cudaFuncAttributeMaxDynamicSharedMemorySize, attn_smem);

    dim3 blk(256);
    // projections
    gemm_tf32<<<dim3(16, 32), blk, gemm_smem>>>(query, W_QC, QC, NH * DH, D_);
    gemm_tf32<<<dim3(8, 32),  blk, gemm_smem>>>(query, W_QR, QR, NH * DR, D_);
    gemm_tf32<<<dim3(16, 32), blk, gemm_smem>>>(kv,    W_KC, KC, NH * DH, D_);
    gemm_tf32<<<dim3(8, 32),  blk, gemm_smem>>>(kv,    W_KR, KR, NH * DR, D_);
    gemm_tf32<<<dim3(16, 32), blk, gemm_smem>>>(kv,    W_V,  Vv, NH * DH, D_);

    // RoPE in place
    const int pairs = B_ * M_ * NH * DR / 2;
    rope_kernel<<<(pairs + 255) / 256, 256>>>(QR, pairs, M_ - 1);
    rope_kernel<<<(pairs + 255) / 256, 256>>>(KR, pairs, N_ - 1);

    // attention
    attn_kernel<<<dim3(M_ / 64, NH, B_), 128, attn_smem>>>(QC, QR, KC, KR, Vv, AO);

    // output projection
    gemm_tf32<<<dim3(16, 32), blk, gemm_smem>>>(AO, W_O, out, D_, D_);
}

// round 3
// speedup vs baseline: 1.1768x; 1.1768x over previous
#include <cuda_runtime.h>
#include <math.h>

#define B_  2
#define M_  2048
#define N_  2048
#define D_  2048
#define NH  16
#define DH  128
#define DR  64

// ---------------- scratch (device globals; no runtime allocation) ------------
__device__ float g_QC[(size_t)B_ * M_ * NH * DH];
__device__ float g_QR[(size_t)B_ * M_ * NH * DR];
__device__ float g_KC[(size_t)B_ * N_ * NH * DH];
__device__ float g_KR[(size_t)B_ * N_ * NH * DR];
__device__ float g_V [(size_t)B_ * N_ * NH * DH];
__device__ float g_AO[(size_t)B_ * M_ * NH * DH];

// ---------------- helpers ----------------------------------------------------
__device__ __forceinline__ unsigned f2tf(float x) {
    unsigned y;
    asm("cvt.rna.tf32.f32 %0, %1;" : "=r"(y) : "f"(x));
    return y;
}

__device__ __forceinline__ void mma8(float* c, const unsigned* a, const unsigned* b) {
    asm volatile(
        "mma.sync.aligned.m16n8k8.row.col.f32.tf32.tf32.f32 "
        "{%0,%1,%2,%3},{%4,%5,%6,%7},{%8,%9},{%0,%1,%2,%3};\n"
        : "+f"(c[0]), "+f"(c[1]), "+f"(c[2]), "+f"(c[3])
        : "r"(a[0]), "r"(a[1]), "r"(a[2]), "r"(a[3]), "r"(b[0]), "r"(b[1]));
}

// ---------------- tf32 GEMM: C[R x Cc] = A[R x K] @ W[Cc x K]^T ---------------
// Block tile 128x128, k-tile 32, 256 threads (8 warps, 4x2), double-buffered smem.
#define GSTR 36   // 32 + 4 pad -> conflict-free fragment loads

__global__ __launch_bounds__(256) void gemm_tf32(
    const float* __restrict__ A, const float* __restrict__ W,
    float* __restrict__ C, int Cc, int K)
{
    extern __shared__ unsigned sm[];
    unsigned* As = sm;                 // [2][128][GSTR]
    unsigned* Bs = sm + 2 * 128 * GSTR;

    const int tid  = threadIdx.x;
    const int lane = tid & 31;
    const int w    = tid >> 5;
    const int gid  = lane >> 2;   // groupID
    const int tig  = lane & 3;    // thread-in-group
    const int wr   = (w >> 1) * 32;
    const int wc   = (w & 1) * 64;
    const size_t brow = (size_t)blockIdx.y * 128;
    const size_t bcol = (size_t)blockIdx.x * 128;

    const float* Ag = A + brow * K;
    const float* Wg = W + bcol * K;

    float acc[2][8][4];
#pragma unroll
    for (int i = 0; i < 2; i++)
#pragma unroll
        for (int j = 0; j < 8; j++)
#pragma unroll
            for (int k = 0; k < 4; k++) acc[i][j][k] = 0.f;

    // preload k-tile 0 into stage 0
#pragma unroll
    for (int i = 0; i < 4; i++) {
        int idx = tid + i * 256;
        int r = idx >> 3, c = (idx & 7) * 4;
        float4 va = *(const float4*)(Ag + (size_t)r * K + c);
        float4 vb = *(const float4*)(Wg + (size_t)r * K + c);
        unsigned* pa = As + r * GSTR + c;
        pa[0] = f2tf(va.x); pa[1] = f2tf(va.y); pa[2] = f2tf(va.z); pa[3] = f2tf(va.w);
        unsigned* pb = Bs + r * GSTR + c;
        pb[0] = f2tf(vb.x); pb[1] = f2tf(vb.y); pb[2] = f2tf(vb.z); pb[3] = f2tf(vb.w);
    }
    __syncthreads();

    const int nk = K >> 5;
    int st = 0;
    for (int kt = 0; kt < nk; ++kt) {
        float4 ra[4], rb[4];
        if (kt + 1 < nk) {
            const float* Ag2 = Ag + (kt + 1) * 32;
            const float* Wg2 = Wg + (kt + 1) * 32;
#pragma unroll
            for (int i = 0; i < 4; i++) {
                int idx = tid + i * 256;
                int r = idx >> 3, c = (idx & 7) * 4;
                ra[i] = *(const float4*)(Ag2 + (size_t)r * K + c);
                rb[i] = *(const float4*)(Wg2 + (size_t)r * K + c);
            }
        }
        const unsigned* Ac = As + st * 128 * GSTR;
        const unsigned* Bc = Bs + st * 128 * GSTR;
#pragma unroll
        for (int kc = 0; kc < 4; ++kc) {
            const int k = kc * 8;
            unsigned af[2][4];
#pragma unroll
            for (int mt = 0; mt < 2; ++mt) {
                const unsigned* p = Ac + (wr + mt * 16 + gid) * GSTR + k + tig;
                af[mt][0] = p[0];
                af[mt][2] = p[4];
                af[mt][1] = p[8 * GSTR];
                af[mt][3] = p[8 * GSTR + 4];
            }
#pragma unroll
            for (int nt = 0; nt < 8; ++nt) {
                unsigned bf[2];
                const unsigned* q = Bc + (wc + nt * 8 + gid) * GSTR + k + tig;
                bf[0] = q[0];
                bf[1] = q[4];
                mma8(acc[0][nt], af[0], bf);
                mma8(acc[1][nt], af[1], bf);
            }
        }
        if (kt + 1 < nk) {
            unsigned* An = As + (st ^ 1) * 128 * GSTR;
            unsigned* Bn = Bs + (st ^ 1) * 128 * GSTR;
#pragma unroll
            for (int i = 0; i < 4; i++) {
                int idx = tid + i * 256;
                int r = idx >> 3, c = (idx & 7) * 4;
                unsigned* pa = An + r * GSTR + c;
                pa[0] = f2tf(ra[i].x); pa[1] = f2tf(ra[i].y); pa[2] = f2tf(ra[i].z); pa[3] = f2tf(ra[i].w);
                unsigned* pb = Bn + r * GSTR + c;
                pb[0] = f2tf(rb[i].x); pb[1] = f2tf(rb[i].y); pb[2] = f2tf(rb[i].z); pb[3] = f2tf(rb[i].w);
            }
        }
        __syncthreads();
        st ^= 1;
    }

#pragma unroll
    for (int mt = 0; mt < 2; ++mt)
#pragma unroll
        for (int nt = 0; nt < 8; ++nt) {
            size_t row = brow + wr + mt * 16 + gid;
            size_t col = bcol + wc + nt * 8 + 2 * tig;
            *(float2*)(C + row * Cc + col)       = make_float2(acc[mt][nt][0], acc[mt][nt][1]);
            *(float2*)(C + (row + 8) * Cc + col) = make_float2(acc[mt][nt][2], acc[mt][nt][3]);
        }
}

// ---------------- RoPE (in-place, interleaved pairs) --------------------------
__global__ void rope_kernel(float* __restrict__ x, int nPairs, int seqmask) {
    int idx = blockIdx.x * blockDim.x + threadIdx.x;
    if (idx >= nPairs) return;
    int tok = idx >> 9;          // NH*DR/2 = 512 pairs per token
    int p   = idx & 511;
    int i   = p & 31;            // pair index within head
    int pos = tok & seqmask;     // position within sequence
    // inv_freq = theta^(-i/32), theta = 1e6 ; ln(1e6) = 13.815511
    float inv = expf(-(float)i * (13.8155106f / 32.0f));
    float ang = (float)pos * inv;
    float s, c;
    sincosf(ang, &s, &c);
    size_t base = (size_t)tok * (NH * DR) + 2 * p;
    float x0 = x[base], x1 = x[base + 1];
    x[base]     = x0 * c - x1 * s;
    x[base + 1] = x1 * c + x0 * s;
}

// ---------------- flash attention (tf32 mma) ----------------------------------
// grid (M/128, NH, B), 256 threads (8 warps). Each warp owns 16 q-rows x 64 cols.
// Q tile 128 x 192, K/V tile 64 rows.
#define QSTR 196   // 192 + 4
#define VSTR 132   // 128 + 4
#define PSTR 68    // 64 + 4
#define LOG2E 1.44269504f

__global__ __launch_bounds__(256) void attn_kernel(
    const float* __restrict__ QC, const float* __restrict__ QR,
    const float* __restrict__ KC, const float* __restrict__ KR,
    const float* __restrict__ Vg, float* __restrict__ AO)
{
    extern __shared__ unsigned sm[];
    unsigned* Qs = sm;                   // [128][QSTR]
    unsigned* Ks = Qs + 128 * QSTR;      // [64][QSTR]
    unsigned* Vs = Ks + 64 * QSTR;       // [64][VSTR]
    unsigned* Ps = Vs + 64 * VSTR;       // [128][PSTR]

    const int tid  = threadIdx.x;
    const int lane = tid & 31;
    const int w    = tid >> 5;
    const int gid  = lane >> 2;
    const int tig  = lane & 3;
    const int m0 = blockIdx.x * 128;
    const int h  = blockIdx.y;
    const int b  = blockIdx.z;
    const float scale = 0.07216878364870323f; // 1/sqrt(192)

    const float* QCb = QC + ((size_t)b * M_ + m0) * (NH * DH) + h * DH;
    const float* QRb = QR + ((size_t)b * M_ + m0) * (NH * DR) + h * DR;
    const float* KCb = KC + (size_t)b * N_ * (NH * DH) + h * DH;
    const float* KRb = KR + (size_t)b * N_ * (NH * DR) + h * DR;
    const float* Vb  = Vg + (size_t)b * N_ * (NH * DH) + h * DH;

    // load Q tile (128 x 192), scale folded in
#pragma unroll
    for (int i = 0; i < 24; i++) {
        int idx = tid + i * 256;
        int r = idx / 48, j = idx % 48;
        float4 v; int col;
        if (j < 32) { v = *(const float4*)(QCb + (size_t)r * (NH * DH) + j * 4); col = j * 4; }
        else        { v = *(const float4*)(QRb + (size_t)r * (NH * DR) + (j - 32) * 4); col = 128 + (j - 32) * 4; }
        unsigned* p = Qs + r * QSTR + col;
        p[0] = f2tf(v.x * scale); p[1] = f2tf(v.y * scale);
        p[2] = f2tf(v.z * scale); p[3] = f2tf(v.w * scale);
    }

    float o[16][4];
#pragma unroll
    for (int i = 0; i < 16; i++)
#pragma unroll
        for (int j = 0; j < 4; j++) o[i][j] = 0.f;
    const float NEG_INF = __int_as_float(0xff800000);
    float mx0 = NEG_INF, mx1 = NEG_INF, l0 = 0.f, l1 = 0.f;

    for (int n0 = 0; n0 < N_; n0 += 64) {
        __syncthreads();   // previous iteration's consumers done
        // K tile 64 x 192
#pragma unroll
        for (int i = 0; i < 12; i++) {
            int idx = tid + i * 256;
            int r = idx / 48, j = idx % 48;
            float4 v; int col;
            if (j < 32) { v = *(const float4*)(KCb + (size_t)(n0 + r) * (NH * DH) + j * 4); col = j * 4; }
            else        { v = *(const float4*)(KRb + (size_t)(n0 + r) * (NH * DR) + (j - 32) * 4); col = 128 + (j - 32) * 4; }
            unsigned* p = Ks + r * QSTR + col;
            p[0] = f2tf(v.x); p[1] = f2tf(v.y); p[2] = f2tf(v.z); p[3] = f2tf(v.w);
        }
        // V tile 64 x 128
#pragma unroll
        for (int i = 0; i < 8; i++) {
            int idx = tid + i * 256;
            int r = idx >> 5, c = (idx & 31) * 4;
            float4 v = *(const float4*)(Vb + (size_t)(n0 + r) * (NH * DH) + c);
            unsigned* p = Vs + r * VSTR + c;
            p[0] = f2tf(v.x); p[1] = f2tf(v.y); p[2] = f2tf(v.z); p[3] = f2tf(v.w);
        }
        __syncthreads();

        // S = Q @ K^T   (warp w: rows 16w..16w+15, cols 0..63)
        float s[8][4];
#pragma unroll
        for (int i = 0; i < 8; i++)
#pragma unroll
            for (int j = 0; j < 4; j++) s[i][j] = 0.f;
#pragma unroll
        for (int kc = 0; kc < 24; ++kc) {
            const int k = kc * 8;
            unsigned af[4];
            const unsigned* p = Qs + (w * 16 + gid) * QSTR + k + tig;
            af[0] = p[0];
            af[2] = p[4];
            af[1] = p[8 * QSTR];
            af[3] = p[8 * QSTR + 4];
#pragma unroll
            for (int nt = 0; nt < 8; ++nt) {
                unsigned bf[2];
                const unsigned* q = Ks + (nt * 8 + gid) * QSTR + k + tig;
                bf[0] = q[0];
                bf[1] = q[4];
                mma8(s[nt], af, bf);
            }
        }

        // online softmax
        float tm0 = NEG_INF, tm1 = NEG_INF;
#pragma unroll
        for (int nt = 0; nt < 8; ++nt) {
            tm0 = fmaxf(tm0, fmaxf(s[nt][0], s[nt][1]));
            tm1 = fmaxf(tm1, fmaxf(s[nt][2], s[nt][3]));
        }
        tm0 = fmaxf(tm0, __shfl_xor_sync(0xffffffffu, tm0, 1));
        tm0 = fmaxf(tm0, __shfl_xor_sync(0xffffffffu, tm0, 2));
        tm1 = fmaxf(tm1, __shfl_xor_sync(0xffffffffu, tm1, 1));
        tm1 = fmaxf(tm1, __shfl_xor_sync(0xffffffffu, tm1, 2));
        float nm0 = fmaxf(mx0, tm0), nm1 = fmaxf(mx1, tm1);
        float a0 = exp2f((mx0 - nm0) * LOG2E);
        float a1 = exp2f((mx1 - nm1) * LOG2E);

        float rs0 = 0.f, rs1 = 0.f;
        unsigned* pr0 = Ps + (w * 16 + gid) * PSTR;
        unsigned* pr1 = pr0 + 8 * PSTR;
#pragma unroll
        for (int nt = 0; nt < 8; ++nt) {
            float p0 = exp2f((s[nt][0] - nm0) * LOG2E);
            float p1 = exp2f((s[nt][1] - nm0) * LOG2E);
            float p2 = exp2f((s[nt][2] - nm1) * LOG2E);
            float p3 = exp2f((s[nt][3] - nm1) * LOG2E);
            rs0 += p0 + p1; rs1 += p2 + p3;
            pr0[nt * 8 + 2 * tig]     = f2tf(p0);
            pr0[nt * 8 + 2 * tig + 1] = f2tf(p1);
            pr1[nt * 8 + 2 * tig]     = f2tf(p2);
            pr1[nt * 8 + 2 * tig + 1] = f2tf(p3);
        }
        rs0 += __shfl_xor_sync(0xffffffffu, rs0, 1);
        rs0 += __shfl_xor_sync(0xffffffffu, rs0, 2);
        rs1 += __shfl_xor_sync(0xffffffffu, rs1, 1);
        rs1 += __shfl_xor_sync(0xffffffffu, rs1, 2);
        l0 = l0 * a0 + rs0;
        l1 = l1 * a1 + rs1;
        mx0 = nm0; mx1 = nm1;
#pragma unroll
        for (int nt = 0; nt < 16; ++nt) {
            o[nt][0] *= a0; o[nt][1] *= a0;
            o[nt][2] *= a1; o[nt][3] *= a1;
        }
        __syncwarp();

        // O += P @ V   (warp w: rows 16w.., all 128 output cols)
#pragma unroll
        for (int kc = 0; kc < 8; ++kc) {
            unsigned af[4];
            const unsigned* p = Ps + (w * 16 + gid) * PSTR + kc * 8 + tig;
            af[0] = p[0];
            af[2] = p[4];
            af[1] = p[8 * PSTR];
            af[3] = p[8 * PSTR + 4];
#pragma unroll
            for (int nt = 0; nt < 16; ++nt) {
                unsigned bf[2];
                const unsigned* q = Vs + (kc * 8 + tig) * VSTR + nt * 8 + gid;
                bf[0] = q[0];
                bf[1] = q[4 * VSTR];
                mma8(o[nt], af, bf);
            }
        }
    }

    // epilogue
    float i0 = 1.f / l0, i1 = 1.f / l1;
    float* O0 = AO + ((size_t)b * M_ + m0 + w * 16 + gid) * (NH * DH) + h * DH;
    float* O1 = O0 + (size_t)8 * (NH * DH);
#pragma unroll
    for (int nt = 0; nt < 16; ++nt) {
        int col = nt * 8 + 2 * tig;
        *(float2*)(O0 + col) = make_float2(o[nt][0] * i0, o[nt][1] * i0);
        *(float2*)(O1 + col) = make_float2(o[nt][2] * i1, o[nt][3] * i1);
    }
}

// ---------------- launcher ----------------------------------------------------
extern "C" void kernel_launch(void* const* d_in, const int* in_sizes, int n_in,
                              void* d_out, int out_size)
{
    const float* query = (const float*)d_in[0];
    const float* kv    = (const float*)d_in[1];
    const float* W_QC  = (const float*)d_in[2];
    const float* W_KC  = (const float*)d_in[3];
    const float* W_QR  = (const float*)d_in[4];
    const float* W_KR  = (const float*)d_in[5];
    const float* W_V   = (const float*)d_in[6];
    const float* W_O   = (const float*)d_in[7];
    float* out = (float*)d_out;

    float *QC, *QR, *KC, *KR, *Vv, *AO;
    cudaGetSymbolAddress((void**)&QC, g_QC);
    cudaGetSymbolAddress((void**)&QR, g_QR);
    cudaGetSymbolAddress((void**)&KC, g_KC);
    cudaGetSymbolAddress((void**)&KR, g_KR);
    cudaGetSymbolAddress((void**)&Vv, g_V);
    cudaGetSymbolAddress((void**)&AO, g_AO);

    const int gemm_smem = 2 * 128 * GSTR * 2 * (int)sizeof(unsigned);          // 73728 B
    const int attn_smem = (128 * QSTR + 64 * QSTR + 64 * VSTR + 128 * PSTR) * (int)sizeof(unsigned); // 219136 B
    cudaFuncSetAttribute(gemm_tf32, cudaFuncAttributeMaxDynamicSharedMemorySize, gemm_smem);
    cudaFuncSetAttribute(attn_kernel, cudaFuncAttributeMaxDynamicSharedMemorySize, attn_smem);

    dim3 blk(256);
    // projections
    gemm_tf32<<<dim3(16, 32), blk, gemm_smem>>>(query, W_QC, QC, NH * DH, D_);
    gemm_tf32<<<dim3(8, 32),  blk, gemm_smem>>>(query, W_QR, QR, NH * DR, D_);
    gemm_tf32<<<dim3(16, 32), blk, gemm_smem>>>(kv,    W_KC, KC, NH * DH, D_);
    gemm_tf32<<<dim3(8, 32),  blk, gemm_smem>>>(kv,    W_KR, KR, NH * DR, D_);
    gemm_tf32<<<dim3(16, 32), blk, gemm_smem>>>(kv,    W_V,  Vv, NH * DH, D_);

    // RoPE in place
    const int pairs = B_ * M_ * NH * DR / 2;
    rope_kernel<<<(pairs + 255) / 256, 256>>>(QR, pairs, M_ - 1);
    rope_kernel<<<(pairs + 255) / 256, 256>>>(KR, pairs, N_ - 1);

    // attention
    attn_kernel<<<dim3(M_ / 128, NH, B_), 256, attn_smem>>>(QC, QR, KC, KR, Vv, AO);

    // output projection
    gemm_tf32<<<dim3(16, 32), blk, gemm_smem>>>(AO, W_O, out, D_, D_);
}